// round 3
// baseline (speedup 1.0000x reference)
#include <cuda_runtime.h>
#include <cstdint>

#define Hdim 768
#define KC 64
#define CHUNKS 12
#define T1 144
#define NP1 1369            // 37*37
#define STRIDE 68           // 64 + 4 pad floats
#define BUFS (72*STRIDE)    // 4896 floats

// persistent smem (floats)
#define OXY 0                 // 3 buffers
#define OGW (3*BUFS)          // 14688 : g*w vector 768
#define OWP (OGW+768)         // 15456 : per-thread gw partials 144*2
#define SM_FLOATS (OWP+288)   // 15744 floats = 62976 B
#define SM_BYTES (SM_FLOATS*4)

// alias region (valid only after main loop; overlays buffer 0)
#define OCS 0                 // couplings 1369
#define OEC 1369              // exp(couplings) 1369
#define OST 2738              // stat partials 144*3
#define ORN 3170              // rsqrt norms 72
#define ODU 3242              // dustbin*10 72
#define OU  3314
#define OV  3351
#define OEU 3388
#define OEV 3425
#define OTOT 3462

#define NORMC (-4.27666611901605529f)   // -log(72)
#define LMD   (-0.69314718055994531f)   // log(36) - log(72)

__device__ __forceinline__ void fma2(unsigned long long &d,
                                     unsigned long long a,
                                     unsigned long long b) {
    asm volatile("fma.rn.f32x2 %0, %1, %2, %0;" : "+l"(d) : "l"(a), "l"(b));
}
__device__ __forceinline__ float lo32(unsigned long long a) {
    return __uint_as_float((unsigned)a);
}
__device__ __forceinline__ float hi32(unsigned long long a) {
    return __uint_as_float((unsigned)(a >> 32));
}
__device__ __forceinline__ void cp16(float* dst, const float* src) {
    unsigned s = (unsigned)__cvta_generic_to_shared(dst);
    asm volatile("cp.async.cg.shared.global [%0], [%1], 16;" :: "r"(s), "l"(src));
}

// load one 72x64 chunk (x rows 0-35, y rows 36-71)
__device__ __forceinline__ void load_chunk(float* buf, const float* xb,
                                           const float* yb, int koff, int t)
{
    #pragma unroll
    for (int rr = 0; rr < 8; ++rr) {
        int idx = t + T1*rr;              // 0..1151
        int row = idx >> 4;
        int c4  = idx & 15;
        const float* src = (row < 36 ? xb + row*Hdim
                                     : yb + (row-36)*Hdim) + koff + c4*4;
        cp16(buf + row*STRIDE + c4*4, src);
    }
    asm volatile("cp.async.commit_group;");
}

// ======================= fused kernel ===================================
__global__ void __launch_bounds__(T1, 3)
k_fused(const float* __restrict__ X, const float* __restrict__ Y,
        const float* __restrict__ G, const float* __restrict__ Bln,
        const float* __restrict__ W, const float* __restrict__ Blin,
        float* __restrict__ out, int B)
{
    extern __shared__ float sm[];
    const int t = threadIdx.x;
    const int b = blockIdx.x;
    const float* xb = X + (size_t)b * (36*Hdim);
    const float* yb = Y + (size_t)b * (36*Hdim);

    const int ks = t & 3;               // k-slice 0..3
    const int tile = t >> 2;            // 0..35
    const int m0 = (tile / 6) * 6;
    const int n0 = (tile % 6) * 6;

    // prologue: prefetch chunks 0,1
    load_chunk(sm + OXY,        xb, yb, 0,  t);
    load_chunk(sm + OXY + BUFS, xb, yb, KC, t);

    // g*w vector + per-thread partials (overlaps DRAM)
    {
        float sgw = 0.f, sbw = 0.f;
        for (int h = t; h < Hdim; h += T1) {
            float wv = W[h];
            float gv = G[h]*wv;
            sm[OGW + h] = gv;
            sgw += gv;
            sbw += Bln[h]*wv;
        }
        sm[OWP + t*2 + 0] = sgw;
        sm[OWP + t*2 + 1] = sbw;
    }

    unsigned long long acc[36];
    #pragma unroll
    for (int e = 0; e < 36; ++e) acc[e] = 0ULL;
    unsigned long long sx2 = 0ULL, sxx2 = 0ULL, sxg2 = 0ULL;
    const unsigned long long ONES2 = 0x3f8000003f800000ULL;

    #pragma unroll 1
    for (int ch = 0; ch < CHUNKS; ++ch) {
        if (ch < CHUNKS-1) asm volatile("cp.async.wait_group 1;");
        else               asm volatile("cp.async.wait_group 0;");
        __syncthreads();
        if (ch + 2 < CHUNKS)
            load_chunk(sm + OXY + ((ch+2)%3)*BUFS, xb, yb, (ch+2)*KC, t);

        const float* xy = sm + OXY + (ch%3)*BUFS;

        // ---- GEMM: 6x6 register tile, f32x2 ----
        #pragma unroll
        for (int q = 0; q < 4; ++q) {
            const int j4 = (ks + q*4) * 4;
            ulonglong2 xv[6], yv[6];
            #pragma unroll
            for (int i = 0; i < 6; ++i)
                xv[i] = *reinterpret_cast<const ulonglong2*>(xy + (m0+i)*STRIDE + j4);
            #pragma unroll
            for (int j = 0; j < 6; ++j)
                yv[j] = *reinterpret_cast<const ulonglong2*>(xy + (36+n0+j)*STRIDE + j4);
            #pragma unroll
            for (int i = 0; i < 6; ++i)
                #pragma unroll
                for (int j = 0; j < 6; ++j) {
                    fma2(acc[i*6+j], xv[i].x, yv[j].x);
                    fma2(acc[i*6+j], xv[i].y, yv[j].y);
                }
        }

        // ---- per-row stats: thread (t>>1) = row, (t&1) = half, f32x2 ----
        {
            const ulonglong2* rp = reinterpret_cast<const ulonglong2*>(
                xy + (t>>1)*STRIDE + (t&1)*32);
            const ulonglong2* gp = reinterpret_cast<const ulonglong2*>(
                sm + OGW + ch*KC + (t&1)*32);
            #pragma unroll
            for (int j = 0; j < 8; ++j) {
                ulonglong2 v = rp[j];
                ulonglong2 g = gp[j];
                fma2(sx2,  v.x, ONES2);  fma2(sx2,  v.y, ONES2);
                fma2(sxx2, v.x, v.x);    fma2(sxx2, v.y, v.y);
                fma2(sxg2, v.x, g.x);    fma2(sxg2, v.y, g.y);
            }
        }
    }
    __syncthreads();   // all buffer reads done; alias region now writable

    // stats partials -> smem (indexed by t: row=t>>1, half=t&1)
    sm[OST + t*3 + 0] = lo32(sx2)  + hi32(sx2);
    sm[OST + t*3 + 1] = lo32(sxx2) + hi32(sxx2);
    sm[OST + t*3 + 2] = lo32(sxg2) + hi32(sxg2);

    // reduce GEMM accumulators across 4 k-slices
    float accf[36];
    #pragma unroll
    for (int e = 0; e < 36; ++e) {
        float s = lo32(acc[e]) + hi32(acc[e]);
        s += __shfl_down_sync(0xffffffffu, s, 2, 4);
        s += __shfl_down_sync(0xffffffffu, s, 1, 4);
        accf[e] = s;
    }
    __syncthreads();

    // per-row finalize (72 rows: x rows 0-35, y rows 36-71)
    if (t < 72) {
        float Sx  = sm[OST + (2*t)*3 + 0] + sm[OST + (2*t+1)*3 + 0];
        float Sxx = sm[OST + (2*t)*3 + 1] + sm[OST + (2*t+1)*3 + 1];
        float Sxg = sm[OST + (2*t)*3 + 2] + sm[OST + (2*t+1)*3 + 2];
        float Sgw = 0.f, Sbw = 0.f;
        for (int j = 0; j < T1; ++j) {
            Sgw += sm[OWP + j*2 + 0];
            Sbw += sm[OWP + j*2 + 1];
        }
        sm[ORN + t] = rsqrtf(Sxx);
        float mu  = Sx * (1.f/768.f);
        float var = Sxx * (1.f/768.f) - mu*mu;
        float rsd = rsqrtf(var + 1e-5f);
        sm[ODU + t] = tanhf((Sxg - mu*Sgw)*rsd + Sbw + Blin[0]) * 10.f;
    }
    if (t < 37) {
        sm[OU + t] = 0.f; sm[OV + t] = 0.f;
        sm[OEU + t] = 1.f; sm[OEV + t] = 1.f;
    }
    if (t == 0) sm[OTOT] = 0.f;
    __syncthreads();

    // assemble couplings (already /REG via *10)
    if (ks == 0) {
        #pragma unroll
        for (int i = 0; i < 6; ++i) {
            float rx = sm[ORN + m0 + i];
            #pragma unroll
            for (int j = 0; j < 6; ++j)
                sm[OCS + (m0+i)*37 + (n0+j)] =
                    accf[i*6+j] * rx * sm[ORN + 36 + n0 + j] * 10.f;
        }
    }
    if (t < 36) {
        sm[OCS + t*37 + 36] = sm[ODU + t];
        sm[OCS + 36*37 + t] = sm[ODU + 36 + t];
    }
    if (t == 0) sm[OCS + 36*37 + 36] = -1000.f;
    __syncthreads();

    // exp(couplings)
    for (int i = t; i < NP1; i += T1) sm[OEC + i] = __expf(sm[OCS + i]);
    __syncthreads();

    // ---- Sinkhorn: 20 iterations, exp-domain dot products ----
    const int m = t;
    const bool act = t < 37;
    const float lr = (m < 36) ? NORMC : LMD;   // log_mu == log_nu (M==N)
    #pragma unroll 1
    for (int it = 0; it < 20; ++it) {
        if (act) {
            const float* er = sm + OEC + m*37;
            float s0=0.f, s1=0.f, s2=0.f, s3=0.f;
            #pragma unroll
            for (int n = 0; n < 36; n += 4) {
                s0 = fmaf(er[n+0], sm[OEV+n+0], s0);
                s1 = fmaf(er[n+1], sm[OEV+n+1], s1);
                s2 = fmaf(er[n+2], sm[OEV+n+2], s2);
                s3 = fmaf(er[n+3], sm[OEV+n+3], s3);
            }
            s0 = fmaf(er[36], sm[OEV+36], s0);
            float uu = lr - __logf((s0+s1)+(s2+s3));
            sm[OU + m] = uu;
            sm[OEU + m] = __expf(uu);
        }
        __syncthreads();
        if (act) {
            const float* ecc = sm + OEC + m;
            float s0=0.f, s1=0.f, s2=0.f, s3=0.f;
            #pragma unroll
            for (int n = 0; n < 36; n += 4) {
                s0 = fmaf(ecc[(n+0)*37], sm[OEU+n+0], s0);
                s1 = fmaf(ecc[(n+1)*37], sm[OEU+n+1], s1);
                s2 = fmaf(ecc[(n+2)*37], sm[OEU+n+2], s2);
                s3 = fmaf(ecc[(n+3)*37], sm[OEU+n+3], s3);
            }
            s0 = fmaf(ecc[36*37], sm[OEU+36], s0);
            float vv = lr - __logf((s0+s1)+(s2+s3));
            sm[OV + m] = vv;
            sm[OEV + m] = __expf(vv);
        }
        __syncthreads();
    }

    // ---- epilogue: Z + total;  exp(Z) = 72 * ec * eu * ev ----
    float* ob = out + (size_t)b * NP1;
    float part = 0.f;
    for (int i = t; i < NP1; i += T1) {
        int mm = i / 37;
        int nn = i - mm*37;
        float cc = sm[OCS + i];
        ob[i] = cc + sm[OU + mm] + sm[OV + nn] - NORMC;
        if (mm < 36 && nn < 36)
            part += sm[OEC + i] * sm[OEU + mm] * sm[OEV + nn] * cc;
    }
    atomicAdd(&sm[OTOT], part * 72.f);
    __syncthreads();
    if (t == 0) out[(size_t)B*NP1 + b] = sm[OTOT];
}

// ======================= launch =========================================
extern "C" void kernel_launch(void* const* d_in, const int* in_sizes, int n_in,
                              void* d_out, int out_size)
{
    const float* x  = (const float*)d_in[0];
    const float* y  = (const float*)d_in[1];
    const float* g  = (const float*)d_in[2];
    const float* bb = (const float*)d_in[3];
    const float* w  = (const float*)d_in[4];
    const float* bl = (const float*)d_in[5];
    const int B = in_sizes[0] / (36 * Hdim);
    float* out = (float*)d_out;

    cudaFuncSetAttribute(k_fused,
                         cudaFuncAttributeMaxDynamicSharedMemorySize, SM_BYTES);
    k_fused<<<B, T1, SM_BYTES>>>(x, y, g, bb, w, bl, out, B);
}

// round 4
// speedup vs baseline: 1.0002x; 1.0002x over previous
#include <cuda_runtime.h>
#include <cstdint>

#define Hdim 768
#define KC 64
#define CHUNKS 12
#define T1 144
#define NP1 1369            // 37*37
#define STRIDE 68           // 64 + 4 pad floats
#define BUFS (72*STRIDE)    // 4896 floats

// persistent smem (floats)
#define OXY 0                 // 3 buffers
#define OGW (3*BUFS)          // 14688 : g*w vector 768
#define OWP (OGW+768)         // 15456 : per-thread gw partials 144*2
#define SM_FLOATS (OWP+288)   // 15744 floats = 62976 B
#define SM_BYTES (SM_FLOATS*4)

// alias region (valid only after main loop; overlays buffer 0)
#define OCS 0                 // couplings 1369
#define OEC 1369              // exp(couplings) 1369
#define OST 2738              // stat partials 144*3
#define ORN 3170              // rsqrt norms 72
#define ODU 3242              // dustbin*10 72
#define OU  3314
#define OV  3351
#define OEU 3388
#define OEV 3425
#define OTOT 3462

#define NORMC (-4.27666611901605529f)   // -log(72)
#define LMD   (-0.69314718055994531f)   // log(36) - log(72)

__device__ __forceinline__ void fma2(unsigned long long &d,
                                     unsigned long long a,
                                     unsigned long long b) {
    asm volatile("fma.rn.f32x2 %0, %1, %2, %0;" : "+l"(d) : "l"(a), "l"(b));
}
__device__ __forceinline__ float lo32(unsigned long long a) {
    return __uint_as_float((unsigned)a);
}
__device__ __forceinline__ float hi32(unsigned long long a) {
    return __uint_as_float((unsigned)(a >> 32));
}
__device__ __forceinline__ void cp16(float* dst, const float* src) {
    unsigned s = (unsigned)__cvta_generic_to_shared(dst);
    asm volatile("cp.async.cg.shared.global [%0], [%1], 16;" :: "r"(s), "l"(src));
}

// load one 72x64 chunk (x rows 0-35, y rows 36-71)
__device__ __forceinline__ void load_chunk(float* buf, const float* xb,
                                           const float* yb, int koff, int t)
{
    #pragma unroll
    for (int rr = 0; rr < 8; ++rr) {
        int idx = t + T1*rr;              // 0..1151
        int row = idx >> 4;
        int c4  = idx & 15;
        const float* src = (row < 36 ? xb + row*Hdim
                                     : yb + (row-36)*Hdim) + koff + c4*4;
        cp16(buf + row*STRIDE + c4*4, src);
    }
    asm volatile("cp.async.commit_group;");
}

// ======================= fused kernel ===================================
__global__ void __launch_bounds__(T1, 3)
k_fused(const float* __restrict__ X, const float* __restrict__ Y,
        const float* __restrict__ G, const float* __restrict__ Bln,
        const float* __restrict__ W, const float* __restrict__ Blin,
        float* __restrict__ out, int B)
{
    extern __shared__ float sm[];
    const int t = threadIdx.x;
    const int b = blockIdx.x;
    const float* xb = X + (size_t)b * (36*Hdim);
    const float* yb = Y + (size_t)b * (36*Hdim);

    const int ks = t & 3;               // k-slice 0..3
    const int tile = t >> 2;            // 0..35
    const int m0 = (tile / 6) * 6;
    const int n0 = (tile % 6) * 6;

    // prologue: prefetch chunks 0,1
    load_chunk(sm + OXY,        xb, yb, 0,  t);
    load_chunk(sm + OXY + BUFS, xb, yb, KC, t);

    // g*w vector + per-thread partials (overlaps DRAM)
    {
        float sgw = 0.f, sbw = 0.f;
        for (int h = t; h < Hdim; h += T1) {
            float wv = W[h];
            float gv = G[h]*wv;
            sm[OGW + h] = gv;
            sgw += gv;
            sbw += Bln[h]*wv;
        }
        sm[OWP + t*2 + 0] = sgw;
        sm[OWP + t*2 + 1] = sbw;
    }

    unsigned long long acc[36];
    #pragma unroll
    for (int e = 0; e < 36; ++e) acc[e] = 0ULL;
    unsigned long long sx2 = 0ULL, sxx2 = 0ULL, sxg2 = 0ULL;
    const unsigned long long ONES2 = 0x3f8000003f800000ULL;

    #pragma unroll 1
    for (int ch = 0; ch < CHUNKS; ++ch) {
        if (ch < CHUNKS-1) asm volatile("cp.async.wait_group 1;");
        else               asm volatile("cp.async.wait_group 0;");
        __syncthreads();
        if (ch + 2 < CHUNKS)
            load_chunk(sm + OXY + ((ch+2)%3)*BUFS, xb, yb, (ch+2)*KC, t);

        const float* xy = sm + OXY + (ch%3)*BUFS;

        // ---- GEMM: 6x6 register tile, f32x2 ----
        #pragma unroll
        for (int q = 0; q < 4; ++q) {
            const int j4 = (ks + q*4) * 4;
            ulonglong2 xv[6], yv[6];
            #pragma unroll
            for (int i = 0; i < 6; ++i)
                xv[i] = *reinterpret_cast<const ulonglong2*>(xy + (m0+i)*STRIDE + j4);
            #pragma unroll
            for (int j = 0; j < 6; ++j)
                yv[j] = *reinterpret_cast<const ulonglong2*>(xy + (36+n0+j)*STRIDE + j4);
            #pragma unroll
            for (int i = 0; i < 6; ++i)
                #pragma unroll
                for (int j = 0; j < 6; ++j) {
                    fma2(acc[i*6+j], xv[i].x, yv[j].x);
                    fma2(acc[i*6+j], xv[i].y, yv[j].y);
                }
        }

        // ---- per-row stats: thread (t>>1) = row, (t&1) = half, f32x2 ----
        {
            const ulonglong2* rp = reinterpret_cast<const ulonglong2*>(
                xy + (t>>1)*STRIDE + (t&1)*32);
            const ulonglong2* gp = reinterpret_cast<const ulonglong2*>(
                sm + OGW + ch*KC + (t&1)*32);
            #pragma unroll
            for (int j = 0; j < 8; ++j) {
                ulonglong2 v = rp[j];
                ulonglong2 g = gp[j];
                fma2(sx2,  v.x, ONES2);  fma2(sx2,  v.y, ONES2);
                fma2(sxx2, v.x, v.x);    fma2(sxx2, v.y, v.y);
                fma2(sxg2, v.x, g.x);    fma2(sxg2, v.y, g.y);
            }
        }
    }
    __syncthreads();   // all buffer reads done; alias region now writable

    // stats partials -> smem (indexed by t: row=t>>1, half=t&1)
    sm[OST + t*3 + 0] = lo32(sx2)  + hi32(sx2);
    sm[OST + t*3 + 1] = lo32(sxx2) + hi32(sxx2);
    sm[OST + t*3 + 2] = lo32(sxg2) + hi32(sxg2);

    // reduce GEMM accumulators across 4 k-slices
    float accf[36];
    #pragma unroll
    for (int e = 0; e < 36; ++e) {
        float s = lo32(acc[e]) + hi32(acc[e]);
        s += __shfl_down_sync(0xffffffffu, s, 2, 4);
        s += __shfl_down_sync(0xffffffffu, s, 1, 4);
        accf[e] = s;
    }
    __syncthreads();

    // per-row finalize (72 rows: x rows 0-35, y rows 36-71)
    if (t < 72) {
        float Sx  = sm[OST + (2*t)*3 + 0] + sm[OST + (2*t+1)*3 + 0];
        float Sxx = sm[OST + (2*t)*3 + 1] + sm[OST + (2*t+1)*3 + 1];
        float Sxg = sm[OST + (2*t)*3 + 2] + sm[OST + (2*t+1)*3 + 2];
        float Sgw = 0.f, Sbw = 0.f;
        for (int j = 0; j < T1; ++j) {
            Sgw += sm[OWP + j*2 + 0];
            Sbw += sm[OWP + j*2 + 1];
        }
        sm[ORN + t] = rsqrtf(Sxx);
        float mu  = Sx * (1.f/768.f);
        float var = Sxx * (1.f/768.f) - mu*mu;
        float rsd = rsqrtf(var + 1e-5f);
        sm[ODU + t] = tanhf((Sxg - mu*Sgw)*rsd + Sbw + Blin[0]) * 10.f;
    }
    if (t < 37) {
        sm[OU + t] = 0.f; sm[OV + t] = 0.f;
        sm[OEU + t] = 1.f; sm[OEV + t] = 1.f;
    }
    if (t == 0) sm[OTOT] = 0.f;
    __syncthreads();

    // assemble couplings (already /REG via *10)
    if (ks == 0) {
        #pragma unroll
        for (int i = 0; i < 6; ++i) {
            float rx = sm[ORN + m0 + i];
            #pragma unroll
            for (int j = 0; j < 6; ++j)
                sm[OCS + (m0+i)*37 + (n0+j)] =
                    accf[i*6+j] * rx * sm[ORN + 36 + n0 + j] * 10.f;
        }
    }
    if (t < 36) {
        sm[OCS + t*37 + 36] = sm[ODU + t];
        sm[OCS + 36*37 + t] = sm[ODU + 36 + t];
    }
    if (t == 0) sm[OCS + 36*37 + 36] = -1000.f;
    __syncthreads();

    // exp(couplings)
    for (int i = t; i < NP1; i += T1) sm[OEC + i] = __expf(sm[OCS + i]);
    __syncthreads();

    // ---- Sinkhorn: 20 iterations, exp-domain dot products ----
    const int m = t;
    const bool act = t < 37;
    const float lr = (m < 36) ? NORMC : LMD;   // log_mu == log_nu (M==N)
    #pragma unroll 1
    for (int it = 0; it < 20; ++it) {
        if (act) {
            const float* er = sm + OEC + m*37;
            float s0=0.f, s1=0.f, s2=0.f, s3=0.f;
            #pragma unroll
            for (int n = 0; n < 36; n += 4) {
                s0 = fmaf(er[n+0], sm[OEV+n+0], s0);
                s1 = fmaf(er[n+1], sm[OEV+n+1], s1);
                s2 = fmaf(er[n+2], sm[OEV+n+2], s2);
                s3 = fmaf(er[n+3], sm[OEV+n+3], s3);
            }
            s0 = fmaf(er[36], sm[OEV+36], s0);
            float uu = lr - __logf((s0+s1)+(s2+s3));
            sm[OU + m] = uu;
            sm[OEU + m] = __expf(uu);
        }
        __syncthreads();
        if (act) {
            const float* ecc = sm + OEC + m;
            float s0=0.f, s1=0.f, s2=0.f, s3=0.f;
            #pragma unroll
            for (int n = 0; n < 36; n += 4) {
                s0 = fmaf(ecc[(n+0)*37], sm[OEU+n+0], s0);
                s1 = fmaf(ecc[(n+1)*37], sm[OEU+n+1], s1);
                s2 = fmaf(ecc[(n+2)*37], sm[OEU+n+2], s2);
                s3 = fmaf(ecc[(n+3)*37], sm[OEU+n+3], s3);
            }
            s0 = fmaf(ecc[36*37], sm[OEU+36], s0);
            float vv = lr - __logf((s0+s1)+(s2+s3));
            sm[OV + m] = vv;
            sm[OEV + m] = __expf(vv);
        }
        __syncthreads();
    }

    // ---- epilogue: Z + total;  exp(Z) = 72 * ec * eu * ev ----
    float* ob = out + (size_t)b * NP1;
    float part = 0.f;
    for (int i = t; i < NP1; i += T1) {
        int mm = i / 37;
        int nn = i - mm*37;
        float cc = sm[OCS + i];
        ob[i] = cc + sm[OU + mm] + sm[OV + nn] - NORMC;
        if (mm < 36 && nn < 36)
            part += sm[OEC + i] * sm[OEU + mm] * sm[OEV + nn] * cc;
    }
    atomicAdd(&sm[OTOT], part * 72.f);
    __syncthreads();
    if (t == 0) out[(size_t)B*NP1 + b] = sm[OTOT];
}

// ======================= launch =========================================
extern "C" void kernel_launch(void* const* d_in, const int* in_sizes, int n_in,
                              void* d_out, int out_size)
{
    const float* x  = (const float*)d_in[0];
    const float* y  = (const float*)d_in[1];
    const float* g  = (const float*)d_in[2];
    const float* bb = (const float*)d_in[3];
    const float* w  = (const float*)d_in[4];
    const float* bl = (const float*)d_in[5];
    const int B = in_sizes[0] / (36 * Hdim);
    float* out = (float*)d_out;

    cudaFuncSetAttribute(k_fused,
                         cudaFuncAttributeMaxDynamicSharedMemorySize, SM_BYTES);
    k_fused<<<B, T1, SM_BYTES>>>(x, y, g, bb, w, bl, out, B);
}

// round 6
// speedup vs baseline: 1.1089x; 1.1087x over previous
#include <cuda_runtime.h>
#include <cstdint>

#define THREADS 256
#define NCH 12              // 768 / 64 floats per chunk
#define NP1 1369

// ---- smem float offsets ----
#define GWF 0               // g*w vector, 768
#define WPF 768             // 8 warps * 2
#define STF 784             // stats partials 144*3
#define RNF 1216            // rsqrt norms 72
#define DUF 1288            // dustbin*10 72
#define UF  1360
#define VF  1397
#define EUF 1434
#define EVF 1471
#define TOTF 1508
#define CSF 1512            // couplings 1369
#define ECF 2881            // exp couplings 1369 -> 4250
#define AOF 4352            // A stages: 3 * 3264 floats (48 rows x 68)
#define BOF 14144           // B stages: 3 * 2720 floats (40 rows x 68)
#define SM_FLOATS 22304
#define SM_BYTES (SM_FLOATS*4)   // 89216

#define NORMC (-4.27666611901605529f)   // -log(72)
#define LMD   (-0.69314718055994531f)   // log(36)-log(72)

__device__ __forceinline__ void fma2(unsigned long long &d,
                                     unsigned long long a,
                                     unsigned long long b) {
    asm volatile("fma.rn.f32x2 %0, %1, %2, %0;" : "+l"(d) : "l"(a), "l"(b));
}
__device__ __forceinline__ float lo32(unsigned long long a){ return __uint_as_float((unsigned)a); }
__device__ __forceinline__ float hi32(unsigned long long a){ return __uint_as_float((unsigned)(a>>32)); }

__device__ __forceinline__ uint32_t f2tf(float f) {
    uint32_t u; asm("cvt.rna.tf32.f32 %0, %1;" : "=r"(u) : "f"(f)); return u;
}
__device__ __forceinline__ void mma1688(float* d, const uint32_t* a, const uint32_t* b) {
    asm volatile(
        "mma.sync.aligned.m16n8k8.row.col.f32.tf32.tf32.f32 "
        "{%0,%1,%2,%3}, {%4,%5,%6,%7}, {%8,%9}, {%0,%1,%2,%3};"
        : "+f"(d[0]), "+f"(d[1]), "+f"(d[2]), "+f"(d[3])
        : "r"(a[0]), "r"(a[1]), "r"(a[2]), "r"(a[3]), "r"(b[0]), "r"(b[1]));
}
__device__ __forceinline__ void cp16(uint32_t dst, const float* src) {
    asm volatile("cp.async.cg.shared.global [%0], [%1], 16;"
                 :: "r"(dst), "l"(src) : "memory");
}

// one 72-row x 64-float chunk: x rows -> A stage rows 0-35, y rows -> B stage rows 0-35
__device__ __forceinline__ void load_chunk(uint32_t smb, const float* xb,
                                           const float* yb, int c, int t) {
    uint32_t sA = smb + AOF*4 + (c%3)*13056;
    uint32_t sB = smb + BOF*4 + (c%3)*10880;
    #pragma unroll
    for (int r = 0; r < 5; ++r) {
        int op = t + THREADS*r;          // 0..1279; 1152 used
        if (op < 1152) {
            int row = op >> 4, c4 = op & 15;
            if (row < 36)
                cp16(sA + row*272 + c4*16, xb + row*768 + c*64 + c4*4);
            else
                cp16(sB + (row-36)*272 + c4*16, yb + (row-36)*768 + c*64 + c4*4);
        }
    }
    asm volatile("cp.async.commit_group;" ::: "memory");
}

// ======================= fused kernel ===================================
__global__ void __launch_bounds__(THREADS)
k_fused(const float* __restrict__ X, const float* __restrict__ Y,
        const float* __restrict__ G, const float* __restrict__ Bln,
        const float* __restrict__ W, const float* __restrict__ Blin,
        float* __restrict__ out, int B)
{
    extern __shared__ __align__(16) float smf[];
    uint32_t smb;
    asm("{ .reg .u64 tt; cvta.to.shared.u64 tt, %1; cvt.u32.u64 %0, tt; }"
        : "=r"(smb) : "l"(smf));
    const int t = threadIdx.x;
    const int w = t >> 5, lid = t & 31;
    const int g = lid >> 2, tig = lid & 3;
    const int b = blockIdx.x;
    const float* xb = X + (size_t)b * 27648;
    const float* yb = Y + (size_t)b * 27648;

    // zero pad rows (A rows 36-47, B rows 36-39, all 3 stages) - never overwritten
    for (int i = t; i < 16*68*3; i += THREADS) {
        int st = i / (16*68); int rem = i - st*(16*68);
        int row = rem / 68, col = rem - row*68;
        if (row < 12) smf[AOF + st*3264 + (36+row)*68 + col] = 0.f;
        else          smf[BOF + st*2720 + (24+row)*68 + col] = 0.f;  // 36+(row-12)
    }

    // prefetch chunks 0,1
    load_chunk(smb, xb, yb, 0, t);
    load_chunk(smb, xb, yb, 1, t);

    // g*w vector + warp partials
    {
        float sgw = 0.f, sbw = 0.f;
        for (int h = t; h < 768; h += THREADS) {
            float wv = W[h];
            float gv = G[h]*wv;
            smf[GWF + h] = gv;
            sgw += gv;
            sbw += Bln[h]*wv;
        }
        #pragma unroll
        for (int o = 16; o > 0; o >>= 1) {
            sgw += __shfl_down_sync(0xffffffffu, sgw, o);
            sbw += __shfl_down_sync(0xffffffffu, sbw, o);
        }
        if (lid == 0) { smf[WPF + w*2] = sgw; smf[WPF + w*2 + 1] = sbw; }
    }

    float acc[3][2][4];
    #pragma unroll
    for (int mt = 0; mt < 3; ++mt)
        #pragma unroll
        for (int nt = 0; nt < 2; ++nt)
            #pragma unroll
            for (int e = 0; e < 4; ++e) acc[mt][nt][e] = 0.f;

    unsigned long long sx2 = 0ULL, sxx2 = 0ULL, sxg2 = 0ULL;
    const unsigned long long ONES2 = 0x3f8000003f800000ULL;
    const int st_id = t - 96;              // stats threads: 96..239
    const int srow = st_id >> 1, shalf = st_id & 1;
    const int ntc = (w < 2) ? 2 : ((w == 2) ? 1 : 0);

    #pragma unroll 1
    for (int c = 0; c < NCH; ++c) {
        if (c < NCH-1) asm volatile("cp.async.wait_group 1;" ::: "memory");
        else           asm volatile("cp.async.wait_group 0;" ::: "memory");
        __syncthreads();

        if (c + 2 < NCH) load_chunk(smb, xb, yb, c+2, t);

        if (w < 3) {
            // ---- tensor-core GEMM: warp w covers n = w*16 .. w*16+ntc*8-1 ----
            const float* As = smf + AOF + (c%3)*3264;
            const float* Bs = smf + BOF + (c%3)*2720 + w*16*68;
            #pragma unroll
            for (int ks = 0; ks < 8; ++ks) {
                const int ko = ks*8 + tig;
                uint32_t a[3][4];
                #pragma unroll
                for (int mt = 0; mt < 3; ++mt) {
                    const float* ar = As + (mt*16 + g)*68 + ko;
                    a[mt][0] = f2tf(ar[0]);
                    a[mt][1] = f2tf(ar[8*68]);
                    a[mt][2] = f2tf(ar[4]);
                    a[mt][3] = f2tf(ar[8*68+4]);
                }
                #pragma unroll
                for (int nt = 0; nt < 2; ++nt) {
                    if (nt < ntc) {
                        const float* br = Bs + (nt*8 + g)*68 + ko;
                        uint32_t bf[2];
                        bf[0] = f2tf(br[0]);
                        bf[1] = f2tf(br[4]);
                        #pragma unroll
                        for (int mt = 0; mt < 3; ++mt)
                            mma1688(acc[mt][nt], a[mt], bf);
                    }
                }
            }
        } else if (st_id >= 0 && st_id < 144) {
            // ---- per-row stats (warps 3-7) ----
            const float* rp = smf + (srow < 36 ? AOF + (c%3)*3264 + srow*68
                                               : BOF + (c%3)*2720 + (srow-36)*68)
                                  + shalf*32;
            const float* gp = smf + GWF + c*64 + shalf*32;
            #pragma unroll
            for (int j = 0; j < 8; ++j) {
                ulonglong2 v = *reinterpret_cast<const ulonglong2*>(rp + j*4);
                ulonglong2 gg = *reinterpret_cast<const ulonglong2*>(gp + j*4);
                fma2(sx2,  v.x, ONES2);  fma2(sx2,  v.y, ONES2);
                fma2(sxx2, v.x, v.x);    fma2(sxx2, v.y, v.y);
                fma2(sxg2, v.x, gg.x);   fma2(sxg2, v.y, gg.y);
            }
        }
    }

    if (st_id >= 0 && st_id < 144) {
        smf[STF + st_id*3 + 0] = lo32(sx2)  + hi32(sx2);
        smf[STF + st_id*3 + 1] = lo32(sxx2) + hi32(sxx2);
        smf[STF + st_id*3 + 2] = lo32(sxg2) + hi32(sxg2);
    }
    __syncthreads();

    // per-row finalize (72 rows)
    if (t < 72) {
        float Sx  = smf[STF + (2*t)*3 + 0] + smf[STF + (2*t+1)*3 + 0];
        float Sxx = smf[STF + (2*t)*3 + 1] + smf[STF + (2*t+1)*3 + 1];
        float Sxg = smf[STF + (2*t)*3 + 2] + smf[STF + (2*t+1)*3 + 2];
        float Sgw = 0.f, Sbw = 0.f;
        #pragma unroll
        for (int j = 0; j < 8; ++j) {
            Sgw += smf[WPF + j*2 + 0];
            Sbw += smf[WPF + j*2 + 1];
        }
        smf[RNF + t] = rsqrtf(Sxx);
        float mu  = Sx * (1.f/768.f);
        float var = Sxx * (1.f/768.f) - mu*mu;
        float rsd = rsqrtf(var + 1e-5f);
        smf[DUF + t] = tanhf((Sxg - mu*Sgw)*rsd + Sbw + Blin[0]) * 10.f;
    }
    if (t < 37) {
        smf[UF + t] = 0.f; smf[VF + t] = 0.f;
        smf[EUF + t] = 1.f; smf[EVF + t] = 1.f;
    }
    if (t == 0) smf[TOTF] = 0.f;
    __syncthreads();

    // write scaled couplings from MMA accumulators
    // C frag: c0=(r,2tig), c1=(r,2tig+1), c2=(r+8,2tig), c3=(r+8,2tig+1)
    if (w < 3) {
        #pragma unroll
        for (int mt = 0; mt < 3; ++mt) {
            #pragma unroll
            for (int nt = 0; nt < 2; ++nt) {
                if (nt < ntc) {
                    int r0 = mt*16 + g;
                    int c0 = w*16 + nt*8 + 2*tig;
                    #pragma unroll
                    for (int e = 0; e < 4; ++e) {
                        int rr = r0 + (e >> 1)*8;
                        int cc = c0 + (e & 1);
                        if (rr < 36 && cc < 36)
                            smf[CSF + rr*37 + cc] =
                                acc[mt][nt][e] * smf[RNF+rr] * smf[RNF+36+cc] * 10.f;
                    }
                }
            }
        }
    }
    if (t < 36) {
        smf[CSF + t*37 + 36] = smf[DUF + t];
        smf[CSF + 36*37 + t] = smf[DUF + 36 + t];
    }
    if (t == 0) smf[CSF + 36*37 + 36] = -1000.f;
    __syncthreads();

    for (int i = t; i < NP1; i += THREADS) smf[ECF + i] = __expf(smf[CSF + i]);
    __syncthreads();

    // ---- Sinkhorn: 20 iterations, exp-domain dot products ----
    const int m = t;
    const bool act = t < 37;
    const float lr = (m < 36) ? NORMC : LMD;
    #pragma unroll 1
    for (int it = 0; it < 20; ++it) {
        if (act) {
            const float* er = smf + ECF + m*37;
            float s0=0.f, s1=0.f, s2=0.f, s3=0.f;
            #pragma unroll
            for (int n = 0; n < 36; n += 4) {
                s0 = fmaf(er[n+0], smf[EVF+n+0], s0);
                s1 = fmaf(er[n+1], smf[EVF+n+1], s1);
                s2 = fmaf(er[n+2], smf[EVF+n+2], s2);
                s3 = fmaf(er[n+3], smf[EVF+n+3], s3);
            }
            s0 = fmaf(er[36], smf[EVF+36], s0);
            float uu = lr - __logf((s0+s1)+(s2+s3));
            smf[UF + m] = uu;
            smf[EUF + m] = __expf(uu);
        }
        __syncthreads();
        if (act) {
            const float* ecc = smf + ECF + m;
            float s0=0.f, s1=0.f, s2=0.f, s3=0.f;
            #pragma unroll
            for (int n = 0; n < 36; n += 4) {
                s0 = fmaf(ecc[(n+0)*37], smf[EUF+n+0], s0);
                s1 = fmaf(ecc[(n+1)*37], smf[EUF+n+1], s1);
                s2 = fmaf(ecc[(n+2)*37], smf[EUF+n+2], s2);
                s3 = fmaf(ecc[(n+3)*37], smf[EUF+n+3], s3);
            }
            s0 = fmaf(ecc[36*37], smf[EUF+36], s0);
            float vv = lr - __logf((s0+s1)+(s2+s3));
            smf[VF + m] = vv;
            smf[EVF + m] = __expf(vv);
        }
        __syncthreads();
    }

    // ---- epilogue: Z + total;  exp(Z) = 72 * ec * eu * ev ----
    float* ob = out + (size_t)b * NP1;
    float part = 0.f;
    for (int i = t; i < NP1; i += THREADS) {
        int mm = i / 37;
        int nn = i - mm*37;
        float cc = smf[CSF + i];
        ob[i] = cc + smf[UF + mm] + smf[VF + nn] - NORMC;
        if (mm < 36 && nn < 36)
            part += smf[ECF + i] * smf[EUF + mm] * smf[EVF + nn] * cc;
    }
    #pragma unroll
    for (int o = 16; o > 0; o >>= 1)
        part += __shfl_down_sync(0xffffffffu, part, o);
    if (lid == 0) atomicAdd(&smf[TOTF], part * 72.f);
    __syncthreads();
    if (t == 0) out[(size_t)B*NP1 + b] = smf[TOTF];
}

// ======================= launch =========================================
extern "C" void kernel_launch(void* const* d_in, const int* in_sizes, int n_in,
                              void* d_out, int out_size)
{
    const float* x  = (const float*)d_in[0];
    const float* y  = (const float*)d_in[1];
    const float* g  = (const float*)d_in[2];
    const float* bb = (const float*)d_in[3];
    const float* w  = (const float*)d_in[4];
    const float* bl = (const float*)d_in[5];
    const int B = in_sizes[0] / (36 * 768);
    float* out = (float*)d_out;

    cudaFuncSetAttribute(k_fused,
                         cudaFuncAttributeMaxDynamicSharedMemorySize, SM_BYTES);
    k_fused<<<B, THREADS, SM_BYTES>>>(x, y, g, bb, w, bl, out, B);
}

// round 7
// speedup vs baseline: 1.5469x; 1.3950x over previous
#include <cuda_runtime.h>
#include <cstdint>

#define THREADS 256
#define NCH 12              // 768 / 64 floats per chunk
#define NP1 1369

// ---- smem float offsets ----
#define GWF 0               // g*w vector, 768
#define WPF 768             // 8 warps * 2
#define STF 784             // stats partials 144*3
#define RNF 1216            // rsqrt norms 72
#define DUF 1288            // dustbin*10 72
#define UF  1360
#define VF  1397
#define EUF 1434
#define EVF 1471
#define TOTF 1508
#define CSF 1512            // couplings 1369
#define ECF 2881            // exp couplings 1369 -> 4250
#define AOF 4352            // A stages: 2 * 3264 floats (48 rows x 68)
#define BOF 10880           // B stages: 2 * 2720 floats (40 rows x 68)
#define SM_FLOATS 16320
#define SM_BYTES (SM_FLOATS*4)   // 65280

#define NORMC (-4.27666611901605529f)   // -log(72)
#define LMD   (-0.69314718055994531f)   // log(36)-log(72)

__device__ __forceinline__ void fma2(unsigned long long &d,
                                     unsigned long long a,
                                     unsigned long long b) {
    asm volatile("fma.rn.f32x2 %0, %1, %2, %0;" : "+l"(d) : "l"(a), "l"(b));
}
__device__ __forceinline__ float lo32(unsigned long long a){ return __uint_as_float((unsigned)a); }
__device__ __forceinline__ float hi32(unsigned long long a){ return __uint_as_float((unsigned)(a>>32)); }

__device__ __forceinline__ uint32_t f2tf(float f) {
    uint32_t u; asm("cvt.rna.tf32.f32 %0, %1;" : "=r"(u) : "f"(f)); return u;
}
__device__ __forceinline__ void mma1688(float* d, const uint32_t* a, const uint32_t* b) {
    asm volatile(
        "mma.sync.aligned.m16n8k8.row.col.f32.tf32.tf32.f32 "
        "{%0,%1,%2,%3}, {%4,%5,%6,%7}, {%8,%9}, {%0,%1,%2,%3};"
        : "+f"(d[0]), "+f"(d[1]), "+f"(d[2]), "+f"(d[3])
        : "r"(a[0]), "r"(a[1]), "r"(a[2]), "r"(a[3]), "r"(b[0]), "r"(b[1]));
}
__device__ __forceinline__ void cp16(uint32_t dst, const float* src) {
    asm volatile("cp.async.cg.shared.global [%0], [%1], 16;"
                 :: "r"(dst), "l"(src) : "memory");
}

// one 72-row x 64-float chunk: x rows -> A stage rows 0-35, y rows -> B rows 0-35
__device__ __forceinline__ void load_chunk(uint32_t smb, const float* xb,
                                           const float* yb, int c, int t) {
    uint32_t sA = smb + AOF*4 + (c&1)*13056;
    uint32_t sB = smb + BOF*4 + (c&1)*10880;
    #pragma unroll
    for (int r = 0; r < 5; ++r) {
        int op = t + THREADS*r;          // 0..1279; 1152 used
        if (op < 1152) {
            int row = op >> 4, c4 = op & 15;
            if (row < 36)
                cp16(sA + row*272 + c4*16, xb + row*768 + c*64 + c4*4);
            else
                cp16(sB + (row-36)*272 + c4*16, yb + (row-36)*768 + c*64 + c4*4);
        }
    }
    asm volatile("cp.async.commit_group;" ::: "memory");
}

// ======================= fused kernel ===================================
__global__ void __launch_bounds__(THREADS, 3)
k_fused(const float* __restrict__ X, const float* __restrict__ Y,
        const float* __restrict__ G, const float* __restrict__ Bln,
        const float* __restrict__ W, const float* __restrict__ Blin,
        float* __restrict__ out, int B)
{
    extern __shared__ __align__(16) float smf[];
    uint32_t smb;
    asm("{ .reg .u64 tt; cvta.to.shared.u64 tt, %1; cvt.u32.u64 %0, tt; }"
        : "=r"(smb) : "l"(smf));
    const int t = threadIdx.x;
    const int w = t >> 5, lid = t & 31;
    const int g = lid >> 2, tig = lid & 3;
    const int b = blockIdx.x;
    const float* xb = X + (size_t)b * 27648;
    const float* yb = Y + (size_t)b * 27648;

    // zero pad rows (A rows 36-47, B rows 36-39, both stages)
    for (int i = t; i < 16*68*2; i += THREADS) {
        int st = i / (16*68); int rem = i - st*(16*68);
        int row = rem / 68, col = rem - row*68;
        if (row < 12) smf[AOF + st*3264 + (36+row)*68 + col] = 0.f;
        else          smf[BOF + st*2720 + (24+row)*68 + col] = 0.f;
    }

    // prefetch chunk 0
    load_chunk(smb, xb, yb, 0, t);

    // g*w vector + warp partials
    {
        float sgw = 0.f, sbw = 0.f;
        for (int h = t; h < 768; h += THREADS) {
            float wv = W[h];
            float gv = G[h]*wv;
            smf[GWF + h] = gv;
            sgw += gv;
            sbw += Bln[h]*wv;
        }
        #pragma unroll
        for (int o = 16; o > 0; o >>= 1) {
            sgw += __shfl_down_sync(0xffffffffu, sgw, o);
            sbw += __shfl_down_sync(0xffffffffu, sbw, o);
        }
        if (lid == 0) { smf[WPF + w*2] = sgw; smf[WPF + w*2 + 1] = sbw; }
    }

    // GEMM decomposition: warps 0-5, warp = (mt = w>>1, nhalf = w&1)
    const int mt  = w >> 1;
    const int nh  = w & 1;
    const int nt0 = nh ? 3 : 0;           // first 8-col tile
    const int ntn = nh ? 2 : 3;           // #tiles
    float acc[3][4];
    #pragma unroll
    for (int j = 0; j < 3; ++j)
        #pragma unroll
        for (int e = 0; e < 4; ++e) acc[j][e] = 0.f;

    // stats: warps 6-7, thread t2 = t-192 handles slices {t2, t2+64, t2<16? t2+128}
    const int t2 = t - 192;
    unsigned long long sx2[3] = {0,0,0}, sxx2[3] = {0,0,0}, sxg2[3] = {0,0,0};
    const unsigned long long ONES2 = 0x3f8000003f800000ULL;

    #pragma unroll 1
    for (int c = 0; c < NCH; ++c) {
        asm volatile("cp.async.wait_group 0;" ::: "memory");
        __syncthreads();
        if (c + 1 < NCH) load_chunk(smb, xb, yb, c+1, t);

        if (w < 6) {
            const float* As = smf + AOF + (c&1)*3264 + (mt*16 + g)*68;
            const float* Bs = smf + BOF + (c&1)*2720 + (nt0*8 + g)*68;
            #pragma unroll
            for (int ks = 0; ks < 8; ++ks) {
                const int ko = ks*8 + tig;
                uint32_t a[4];
                a[0] = f2tf(As[ko]);
                a[1] = f2tf(As[8*68 + ko]);
                a[2] = f2tf(As[ko + 4]);
                a[3] = f2tf(As[8*68 + ko + 4]);
                #pragma unroll
                for (int j = 0; j < 3; ++j) {
                    if (j < ntn) {
                        const float* br = Bs + j*8*68 + ko;
                        uint32_t bf[2];
                        bf[0] = f2tf(br[0]);
                        bf[1] = f2tf(br[4]);
                        mma1688(acc[j], a, bf);
                    }
                }
            }
        } else {
            // stats slices: s -> row = s>>1, half = s&1
            #pragma unroll
            for (int sl = 0; sl < 3; ++sl) {
                int s = t2 + sl*64;
                if (sl < 2 || t2 < 16) {
                    int srow = s >> 1, half = s & 1;
                    const float* rp = smf + (srow < 36
                        ? AOF + (c&1)*3264 + srow*68
                        : BOF + (c&1)*2720 + (srow-36)*68) + half*32;
                    const float* gp = smf + GWF + c*64 + half*32;
                    #pragma unroll
                    for (int j = 0; j < 8; ++j) {
                        ulonglong2 v  = *reinterpret_cast<const ulonglong2*>(rp + j*4);
                        ulonglong2 gg = *reinterpret_cast<const ulonglong2*>(gp + j*4);
                        fma2(sx2[sl],  v.x, ONES2);  fma2(sx2[sl],  v.y, ONES2);
                        fma2(sxx2[sl], v.x, v.x);    fma2(sxx2[sl], v.y, v.y);
                        fma2(sxg2[sl], v.x, gg.x);   fma2(sxg2[sl], v.y, gg.y);
                    }
                }
            }
        }
    }

    if (t2 >= 0) {
        #pragma unroll
        for (int sl = 0; sl < 3; ++sl) {
            int s = t2 + sl*64;
            if (sl < 2 || t2 < 16) {
                smf[STF + s*3 + 0] = lo32(sx2[sl])  + hi32(sx2[sl]);
                smf[STF + s*3 + 1] = lo32(sxx2[sl]) + hi32(sxx2[sl]);
                smf[STF + s*3 + 2] = lo32(sxg2[sl]) + hi32(sxg2[sl]);
            }
        }
    }
    __syncthreads();

    // per-row finalize (72 rows)
    if (t < 72) {
        float Sx  = smf[STF + (2*t)*3 + 0] + smf[STF + (2*t+1)*3 + 0];
        float Sxx = smf[STF + (2*t)*3 + 1] + smf[STF + (2*t+1)*3 + 1];
        float Sxg = smf[STF + (2*t)*3 + 2] + smf[STF + (2*t+1)*3 + 2];
        float Sgw = 0.f, Sbw = 0.f;
        #pragma unroll
        for (int j = 0; j < 8; ++j) {
            Sgw += smf[WPF + j*2 + 0];
            Sbw += smf[WPF + j*2 + 1];
        }
        smf[RNF + t] = rsqrtf(Sxx);
        float mu  = Sx * (1.f/768.f);
        float var = Sxx * (1.f/768.f) - mu*mu;
        float rsd = rsqrtf(var + 1e-5f);
        smf[DUF + t] = tanhf((Sxg - mu*Sgw)*rsd + Sbw + Blin[0]) * 10.f;
    }
    if (t < 37) {
        smf[UF + t] = 0.f; smf[VF + t] = 0.f;
        smf[EUF + t] = 1.f; smf[EVF + t] = 1.f;
    }
    if (t == 0) smf[TOTF] = 0.f;
    __syncthreads();

    // write scaled couplings from MMA accumulators
    if (w < 6) {
        #pragma unroll
        for (int j = 0; j < 3; ++j) {
            if (j < ntn) {
                int r0 = mt*16 + g;
                int c0 = (nt0 + j)*8 + 2*tig;
                #pragma unroll
                for (int e = 0; e < 4; ++e) {
                    int rr = r0 + (e >> 1)*8;
                    int cc = c0 + (e & 1);
                    if (rr < 36 && cc < 36)
                        smf[CSF + rr*37 + cc] =
                            acc[j][e] * smf[RNF+rr] * smf[RNF+36+cc] * 10.f;
                }
            }
        }
    }
    if (t < 36) {
        smf[CSF + t*37 + 36] = smf[DUF + t];
        smf[CSF + 36*37 + t] = smf[DUF + 36 + t];
    }
    if (t == 0) smf[CSF + 36*37 + 36] = -1000.f;
    __syncthreads();

    for (int i = t; i < NP1; i += THREADS) smf[ECF + i] = __expf(smf[CSF + i]);
    __syncthreads();

    // ---- Sinkhorn: warps 0-1 only, named barrier ----
    if (t < 64) {
        const int m = t;
        const bool act = t < 37;
        const float lr = (m < 36) ? NORMC : LMD;
        #pragma unroll 1
        for (int it = 0; it < 20; ++it) {
            if (act) {
                const float* er = smf + ECF + m*37;
                float s0=0.f, s1=0.f, s2=0.f, s3=0.f;
                #pragma unroll
                for (int n = 0; n < 36; n += 4) {
                    s0 = fmaf(er[n+0], smf[EVF+n+0], s0);
                    s1 = fmaf(er[n+1], smf[EVF+n+1], s1);
                    s2 = fmaf(er[n+2], smf[EVF+n+2], s2);
                    s3 = fmaf(er[n+3], smf[EVF+n+3], s3);
                }
                s0 = fmaf(er[36], smf[EVF+36], s0);
                float uu = lr - __logf((s0+s1)+(s2+s3));
                smf[UF + m] = uu;
                smf[EUF + m] = __expf(uu);
            }
            asm volatile("bar.sync 5, 64;" ::: "memory");
            if (act) {
                const float* ecc = smf + ECF + m;
                float s0=0.f, s1=0.f, s2=0.f, s3=0.f;
                #pragma unroll
                for (int n = 0; n < 36; n += 4) {
                    s0 = fmaf(ecc[(n+0)*37], smf[EUF+n+0], s0);
                    s1 = fmaf(ecc[(n+1)*37], smf[EUF+n+1], s1);
                    s2 = fmaf(ecc[(n+2)*37], smf[EUF+n+2], s2);
                    s3 = fmaf(ecc[(n+3)*37], smf[EUF+n+3], s3);
                }
                s0 = fmaf(ecc[36*37], smf[EUF+36], s0);
                float vv = lr - __logf((s0+s1)+(s2+s3));
                smf[VF + m] = vv;
                smf[EVF + m] = __expf(vv);
            }
            asm volatile("bar.sync 5, 64;" ::: "memory");
        }
    }
    __syncthreads();

    // ---- epilogue: Z + total;  exp(Z) = 72 * ec * eu * ev ----
    float* ob = out + (size_t)b * NP1;
    float part = 0.f;
    for (int i = t; i < NP1; i += THREADS) {
        int mm = i / 37;
        int nn = i - mm*37;
        float cc = smf[CSF + i];
        ob[i] = cc + smf[UF + mm] + smf[VF + nn] - NORMC;
        if (mm < 36 && nn < 36)
            part += smf[ECF + i] * smf[EUF + mm] * smf[EVF + nn] * cc;
    }
    #pragma unroll
    for (int o = 16; o > 0; o >>= 1)
        part += __shfl_down_sync(0xffffffffu, part, o);
    if (lid == 0) atomicAdd(&smf[TOTF], part * 72.f);
    __syncthreads();
    if (t == 0) out[(size_t)B*NP1 + b] = smf[TOTF];
}

// ======================= launch =========================================
extern "C" void kernel_launch(void* const* d_in, const int* in_sizes, int n_in,
                              void* d_out, int out_size)
{
    const float* x  = (const float*)d_in[0];
    const float* y  = (const float*)d_in[1];
    const float* g  = (const float*)d_in[2];
    const float* bb = (const float*)d_in[3];
    const float* w  = (const float*)d_in[4];
    const float* bl = (const float*)d_in[5];
    const int B = in_sizes[0] / (36 * 768);
    float* out = (float*)d_out;

    cudaFuncSetAttribute(k_fused,
                         cudaFuncAttributeMaxDynamicSharedMemorySize, SM_BYTES);
    k_fused<<<B, THREADS, SM_BYTES>>>(x, y, g, bb, w, bl, out, B);
}